// round 8
// baseline (speedup 1.0000x reference)
#include <cuda_runtime.h>
#include <cuda_bf16.h>

#define NQ        12
#define BLK       256
#define OUTDIM    256
#define HID       64

__device__ __forceinline__ float2 cmul(float2 a, float2 b) {
    return make_float2(a.x * b.x - a.y * b.y, a.x * b.y + a.y * b.x);
}

__device__ __forceinline__ float2 cfma2(float2 ca, float2 a, float2 cb, float2 b) {
    float2 n;
    n.x = ca.x * a.x - ca.y * a.y + cb.x * b.x - cb.y * b.y;
    n.y = ca.x * a.y + ca.y * a.x + cb.x * b.y + cb.y * b.x;
    return n;
}

// CNOT-ring composite: out bit p (p<=10) = XOR of in bits p..11; bit 11 = XOR of bits 0..10.
__host__ __device__ constexpr int Lmap(int b) {
    int r = 0;
    for (int p = 0; p <= 10; p++) {
        int par = 0;
        for (int q = p; q <= 11; q++) par ^= (b >> q) & 1;
        r |= par << p;
    }
    int par = 0;
    for (int q = 0; q <= 10; q++) par ^= (b >> q) & 1;
    return r | (par << 11);
}
// bit-0-preserving swizzle: xor addr bits 3:1 with addr bits 6:4
__host__ __device__ constexpr int swzB(int x) { return x ^ (((x >> 4) & 7) << 1); }
struct PKt { int v[16]; };
__host__ __device__ constexpr PKt mkPK() {
    PKt t{};
    for (int k = 0; k < 16; k++) t.v[k] = swzB(Lmap(k << 8));
    return t;
}

__global__ __launch_bounds__(BLK) void quantum_reupload_kernel(
    const float* __restrict__ x,    // [B, 48]
    const float* __restrict__ rw,   // [12, 3, 4]
    const float* __restrict__ rb,   // [12, 3]
    const float* __restrict__ w1,   // [64, 12]
    const float* __restrict__ b1,   // [64]
    const float* __restrict__ w2,   // [256, 64]
    const float* __restrict__ b2,   // [256]
    float* __restrict__ out)        // [B, 256]
{
    __shared__ __align__(16) float2 st[4096];   // 32 KB exchange buffer
    __shared__ float2 U[NQ][4];
    __shared__ float  zred[NQ][BLK/32];
    __shared__ float  zfin[NQ];
    __shared__ float  hbuf[HID];

    const int b    = blockIdx.x;
    const int tid  = threadIdx.x;       // 0..255
    const int lane = tid & 31;
    const int warp = tid >> 5;

    constexpr PKt PK = mkPK();          // swzB(L(k<<8)) constants

    // ---- per-batch U3 matrices (layer-invariant) ----
    if (tid < NQ) {
        const float* xb  = x  + b * 48 + tid * 4;
        const float* rwi = rw + tid * 12;
        const float* rbi = rb + tid * 3;
        float x0 = xb[0], x1 = xb[1], x2 = xb[2], x3 = xb[3];
        float th = rbi[0] + rwi[0]*x0 + rwi[1]*x1 + rwi[2] *x2 + rwi[3] *x3;
        float ph = rbi[1] + rwi[4]*x0 + rwi[5]*x1 + rwi[6] *x2 + rwi[7] *x3;
        float lm = rbi[2] + rwi[8]*x0 + rwi[9]*x1 + rwi[10]*x2 + rwi[11]*x3;
        float sh, ch, sp, cp, sl, cl;
        sincosf(th * 0.5f, &sh, &ch);
        sincosf(ph,        &sp, &cp);
        sincosf(lm,        &sl, &cl);
        U[tid][0] = make_float2(ch, 0.f);
        U[tid][1] = make_float2(-cl * sh, -sl * sh);
        U[tid][2] = make_float2( cp * sh,  sp * sh);
        U[tid][3] = make_float2((cp*cl - sp*sl) * ch, (cp*sl + sp*cl) * ch);
    }
    __syncthreads();

    // L(tid part) via suffix parity over 8 bits + bit 11 = parity(tid)
    int y = tid; y ^= y >> 1; y ^= y >> 2; y ^= y >> 4;
    const int Ltid  = (y & 0xFF) | ((y & 1) << 11);
    const int PLtid = swzB(Ltid);
    const int tlo   = tid & 15;
    const int thi   = tid >> 4;
    const int t3    = tid & 7;           // A-mapping f4 slot xor key
    const int cbase = (thi << 8) | tlo;  // C-mapping base
    const int tB    = swzB(tid);         // B-mapping read addr part

    const int t0 = tid & 1, t1 = (tid >> 1) & 1, t2 = (tid >> 2) & 1,
              t3b = (tid >> 3) & 1, t4 = (tid >> 4) & 1, t5 = (tid >> 5) & 1,
              t6 = (tid >> 6) & 1, t7 = (tid >> 7) & 1;

    float2 a[16];
    float4* st4 = (float4*)st;

    // ===== direct build of (perm ∘ layer-0-U3) state in mapping A =====
    // A: p = (tid<<4)|k. amp_A[p] = Π_w f_w(x_{11-w}), x = L^{-1}(p):
    //   w=0: k0^t7   w=1: k0^t6^t7   w=2..7: t(9-w)^t(10-w)
    //   w=8: k3^t0   w=9: k2^k3      w=10: k1^k2   w=11: k0^k1
    {
        float2 base =      (t5 ^ t6) ? U[2][2] : U[2][0];
        base = cmul(base, ((t4 ^ t5) ? U[3][2] : U[3][0]));
        base = cmul(base, ((t3b ^ t4) ? U[4][2] : U[4][0]));
        base = cmul(base, ((t2 ^ t3b) ? U[5][2] : U[5][0]));
        base = cmul(base, ((t1 ^ t2) ? U[6][2] : U[6][0]));
        base = cmul(base, ((t0 ^ t1) ? U[7][2] : U[7][0]));
        float2 baseG[2];
        #pragma unroll
        for (int k0 = 0; k0 < 2; k0++) {
            float2 g = cmul(((k0 ^ t7) ? U[0][2] : U[0][0]),
                            ((k0 ^ t6 ^ t7) ? U[1][2] : U[1][0]));
            baseG[k0] = cmul(base, g);
        }
        float2 Qhi[4], Qlo[4];
        #pragma unroll
        for (int i = 0; i < 4; i++) {
            int m3 = i >> 1, m2 = i & 1;
            Qhi[i] = cmul(((m3 ^ t0) ? U[8][2] : U[8][0]),
                          (m2 ? U[9][2] : U[9][0]));
            int m1 = i >> 1, m0 = i & 1;
            Qlo[i] = cmul((m1 ? U[10][2] : U[10][0]),
                          (m0 ? U[11][2] : U[11][0]));
        }
        #pragma unroll
        for (int k = 0; k < 16; k++) {
            const int k0 = k & 1, k1 = (k >> 1) & 1, k2 = (k >> 2) & 1, k3 = k >> 3;
            const int m3 = k3, m2 = k2 ^ k3, m1 = k1 ^ k2, m0 = k0 ^ k1;
            a[k] = cmul(baseG[k0], cmul(Qhi[(m3 << 1) | m2], Qlo[(m1 << 1) | m0]));
        }
    }

    // ===== layers 1,2 — all gates register-local via 3 mappings =====
    #pragma unroll
    for (int layer = 1; layer < 3; layer++) {
        // A-phase: wires 8..11 on k bit (11-w)
        #pragma unroll
        for (int w = 8; w < 12; w++) {
            const int bp = 11 - w;
            float2 u00 = U[w][0], u01 = U[w][1], u10 = U[w][2], u11 = U[w][3];
            #pragma unroll
            for (int k0 = 0; k0 < 16; k0++) {
                if (k0 & (1 << bp)) continue;
                const int k1 = k0 | (1 << bp);
                float2 a0 = a[k0], a1 = a[k1];
                a[k0] = cfma2(u00, a0, u01, a1);
                a[k1] = cfma2(u10, a0, u11, a1);
            }
        }

        // transpose A -> C (f4 write on A side, f2 read on C side)
        __syncthreads();
        #pragma unroll
        for (int p = 0; p < 8; p++)
            st4[(tid << 3) | (p ^ t3)] =
                make_float4(a[2*p].x, a[2*p].y, a[2*p+1].x, a[2*p+1].y);
        __syncthreads();
        #pragma unroll
        for (int k = 0; k < 16; k++)
            a[k] = st[cbase ^ ((k << 4) | ((k & 7) << 1))];

        // C-phase: wires 4..7 on k bit (7-w)
        #pragma unroll
        for (int w = 4; w < 8; w++) {
            const int bp = 7 - w;
            float2 u00 = U[w][0], u01 = U[w][1], u10 = U[w][2], u11 = U[w][3];
            #pragma unroll
            for (int k0 = 0; k0 < 16; k0++) {
                if (k0 & (1 << bp)) continue;
                const int k1 = k0 | (1 << bp);
                float2 a0 = a[k0], a1 = a[k1];
                a[k0] = cfma2(u00, a0, u01, a1);
                a[k1] = cfma2(u10, a0, u11, a1);
            }
        }

        // transpose C -> B (f2 both sides)
        __syncthreads();
        #pragma unroll
        for (int k = 0; k < 16; k++)
            st[cbase ^ ((k << 4) | ((k & 7) << 1))] = a[k];
        __syncthreads();
        #pragma unroll
        for (int k = 0; k < 16; k++)
            a[k] = st[(k << 8) | tB];

        // B-phase: wires 0..3 on k bit (3-w)
        #pragma unroll
        for (int w = 0; w < 4; w++) {
            const int bp = 3 - w;
            float2 u00 = U[w][0], u01 = U[w][1], u10 = U[w][2], u11 = U[w][3];
            #pragma unroll
            for (int k0 = 0; k0 < 16; k0++) {
                if (k0 & (1 << bp)) continue;
                const int k1 = k0 | (1 << bp);
                float2 a0 = a[k0], a1 = a[k1];
                a[k0] = cfma2(u00, a0, u01, a1);
                a[k1] = cfma2(u10, a0, u11, a1);
            }
        }

        if (layer == 1) {
            // fused CNOT-ring perm back to mapping A (f2 write, f4 read)
            __syncthreads();
            #pragma unroll
            for (int k = 0; k < 16; k++)
                st[PLtid ^ PK.v[k]] = a[k];
            __syncthreads();
            #pragma unroll
            for (int p = 0; p < 8; p++) {
                float4 v = st4[(tid << 3) | (p ^ t3)];
                a[2*p]   = make_float2(v.x, v.y);
                a[2*p+1] = make_float2(v.z, v.w);
            }
        }
    }

    // ===== Z expectations in mapping B, final perm folded into signs =====
    // k-signatures: A=k0^k1^k2 (w0), B=k2^k3 (w1), C=k1^k2^k3 (w2), D=k0^k1^k2^k3 (w>=3)
    float SA = 0.f, SB = 0.f, SC = 0.f, SD = 0.f;
    #pragma unroll
    for (int k = 0; k < 16; k++) {
        float pr = a[k].x * a[k].x + a[k].y * a[k].y;
        const int k0 = k & 1, k1 = (k >> 1) & 1, k2 = (k >> 2) & 1, k3 = k >> 3;
        SA += (k0 ^ k1 ^ k2)      ? -pr : pr;
        SB += (k2 ^ k3)           ? -pr : pr;
        SC += (k1 ^ k2 ^ k3)      ? -pr : pr;
        SD += (k0 ^ k1 ^ k2 ^ k3) ? -pr : pr;
    }
    float zl[NQ];
    {
        const int ptid = __popc(tid) & 1;
        zl[0] = ptid ? -SA : SA;
        zl[1] = SB;
        zl[2] = SC;
        zl[3] = SD;
        #pragma unroll
        for (int w = 4; w < 12; w++) {
            const int j = 11 - w;
            zl[w] = (__popc(tid >> j) & 1) ? -SD : SD;
        }
    }

    #pragma unroll
    for (int w = 0; w < NQ; w++) {
        #pragma unroll
        for (int off = 16; off > 0; off >>= 1)
            zl[w] += __shfl_xor_sync(0xFFFFFFFFu, zl[w], off);
    }
    if (lane == 0) {
        #pragma unroll
        for (int w = 0; w < NQ; w++) zred[w][warp] = zl[w];
    }
    __syncthreads();
    if (tid < NQ) {
        float z = 0.f;
        #pragma unroll
        for (int j = 0; j < BLK / 32; j++) z += zred[tid][j];
        zfin[tid] = z;
    }
    __syncthreads();

    // ---- MLP: relu(z @ w1^T + b1) @ w2^T + b2 ----
    if (tid < HID) {
        float h = b1[tid];
        #pragma unroll
        for (int i = 0; i < NQ; i++) h += zfin[i] * w1[tid * NQ + i];
        hbuf[tid] = fmaxf(h, 0.f);
    }
    __syncthreads();
    float o = b2[tid];
    #pragma unroll
    for (int j = 0; j < HID; j++) o += hbuf[j] * w2[tid * HID + j];
    out[b * OUTDIM + tid] = o;
}

extern "C" void kernel_launch(void* const* d_in, const int* in_sizes, int n_in,
                              void* d_out, int out_size) {
    const float* x  = (const float*)d_in[0];
    const float* rw = (const float*)d_in[1];
    const float* rb = (const float*)d_in[2];
    const float* w1 = (const float*)d_in[3];
    const float* b1 = (const float*)d_in[4];
    const float* w2 = (const float*)d_in[5];
    const float* b2 = (const float*)d_in[6];
    float* out = (float*)d_out;
    int batch = in_sizes[0] / 48;
    quantum_reupload_kernel<<<batch, BLK>>>(x, rw, rb, w1, b1, w2, b2, out);
}

// round 9
// speedup vs baseline: 1.6134x; 1.6134x over previous
#include <cuda_runtime.h>
#include <cuda_bf16.h>

#define NQ        12
#define BLK       256
#define OUTDIM    256
#define HID       64

__device__ __forceinline__ float2 cmul(float2 a, float2 b) {
    return make_float2(a.x * b.x - a.y * b.y, a.x * b.y + a.y * b.x);
}

__device__ __forceinline__ float2 cfma2(float2 ca, float2 a, float2 cb, float2 b) {
    float2 n;
    n.x = ca.x * a.x - ca.y * a.y + cb.x * b.x - cb.y * b.y;
    n.y = ca.x * a.y + ca.y * a.x + cb.x * b.y + cb.y * b.x;
    return n;
}

__device__ __forceinline__ float2 shflx(float2 v, int m) {
    float2 r;
    r.x = __shfl_xor_sync(0xFFFFFFFFu, v.x, m);
    r.y = __shfl_xor_sync(0xFFFFFFFFu, v.y, m);
    return r;
}

// CNOT-ring composite: out bit p (p<=10) = XOR of in bits p..11; bit 11 = XOR of bits 0..10.
__host__ __device__ constexpr int Lmap(int b) {
    int r = 0;
    for (int p = 0; p <= 10; p++) {
        int par = 0;
        for (int q = p; q <= 11; q++) par ^= (b >> q) & 1;
        r |= par << p;
    }
    int par = 0;
    for (int q = 0; q <= 10; q++) par ^= (b >> q) & 1;
    return r | (par << 11);
}
// bit-0-preserving swizzle: xor addr bits 3:1 with addr bits 6:4
__host__ __device__ constexpr int swzB(int x) { return x ^ (((x >> 4) & 7) << 1); }
struct PKt { int v[16]; };
__host__ __device__ constexpr PKt mkPK() {
    PKt t{};
    for (int k = 0; k < 16; k++) t.v[k] = swzB(Lmap(k << 8));
    return t;
}

__global__ __launch_bounds__(BLK, 4) void quantum_reupload_kernel(
    const float* __restrict__ x,    // [B, 48]
    const float* __restrict__ rw,   // [12, 3, 4]
    const float* __restrict__ rb,   // [12, 3]
    const float* __restrict__ w1,   // [64, 12]
    const float* __restrict__ b1,   // [64]
    const float* __restrict__ w2,   // [256, 64]
    const float* __restrict__ b2,   // [256]
    float* __restrict__ out)        // [B, 256]
{
    __shared__ __align__(16) float2 st[4096];   // 32 KB exchange buffer
    __shared__ float2 U[NQ][4];
    __shared__ float  zred[NQ][BLK/32];
    __shared__ float  zfin[NQ];
    __shared__ float  hbuf[HID];

    const int b    = blockIdx.x;
    const int tid  = threadIdx.x;       // 0..255
    const int lane = tid & 31;
    const int warp = tid >> 5;

    constexpr PKt PK = mkPK();          // swzB(L(k<<8)) constants

    // ---- per-batch U3 matrices (layer-invariant) ----
    if (tid < NQ) {
        const float* xb  = x  + b * 48 + tid * 4;
        const float* rwi = rw + tid * 12;
        const float* rbi = rb + tid * 3;
        float x0 = xb[0], x1 = xb[1], x2 = xb[2], x3 = xb[3];
        float th = rbi[0] + rwi[0]*x0 + rwi[1]*x1 + rwi[2] *x2 + rwi[3] *x3;
        float ph = rbi[1] + rwi[4]*x0 + rwi[5]*x1 + rwi[6] *x2 + rwi[7] *x3;
        float lm = rbi[2] + rwi[8]*x0 + rwi[9]*x1 + rwi[10]*x2 + rwi[11]*x3;
        float sh, ch, sp, cp, sl, cl;
        sincosf(th * 0.5f, &sh, &ch);
        sincosf(ph,        &sp, &cp);
        sincosf(lm,        &sl, &cl);
        U[tid][0] = make_float2(ch, 0.f);
        U[tid][1] = make_float2(-cl * sh, -sl * sh);
        U[tid][2] = make_float2( cp * sh,  sp * sh);
        U[tid][3] = make_float2((cp*cl - sp*sl) * ch, (cp*sl + sp*cl) * ch);
    }
    __syncthreads();

    // L(tid part) via suffix parity over 8 bits + bit 11 = parity(tid)
    int y = tid; y ^= y >> 1; y ^= y >> 2; y ^= y >> 4;
    const int Ltid  = (y & 0xFF) | ((y & 1) << 11);
    const int PLtid = swzB(Ltid);
    const int t3    = tid & 7;                          // A-side f4 slot xor key
    const int tB    = tid ^ (((tid >> 4) & 7) << 1);    // B-read addr part

    const int t0 = tid & 1, t1 = (tid >> 1) & 1, t2 = (tid >> 2) & 1,
              t3b = (tid >> 3) & 1, t4 = (tid >> 4) & 1, t5 = (tid >> 5) & 1,
              t6 = (tid >> 6) & 1, t7 = (tid >> 7) & 1;

    float2 a[16];
    float4* st4 = (float4*)st;

    // ===== direct build of (perm ∘ layer-0-U3) state in mapping A =====
    // A: p = (tid<<4)|k. amp_A[p] = Π_w f_w(x_{11-w}), x = L^{-1}(p):
    //   w=0: k0^t7   w=1: k0^t6^t7   w=2..7: t(9-w)^t(10-w)
    //   w=8: k3^t0   w=9: k2^k3      w=10: k1^k2   w=11: k0^k1
    {
        float2 base =      (t5 ^ t6) ? U[2][2] : U[2][0];
        base = cmul(base, ((t4 ^ t5) ? U[3][2] : U[3][0]));
        base = cmul(base, ((t3b ^ t4) ? U[4][2] : U[4][0]));
        base = cmul(base, ((t2 ^ t3b) ? U[5][2] : U[5][0]));
        base = cmul(base, ((t1 ^ t2) ? U[6][2] : U[6][0]));
        base = cmul(base, ((t0 ^ t1) ? U[7][2] : U[7][0]));
        float2 baseG[2];
        #pragma unroll
        for (int k0 = 0; k0 < 2; k0++) {
            float2 g = cmul(((k0 ^ t7) ? U[0][2] : U[0][0]),
                            ((k0 ^ t6 ^ t7) ? U[1][2] : U[1][0]));
            baseG[k0] = cmul(base, g);
        }
        float2 Qhi[4], Qlo[4];
        #pragma unroll
        for (int i = 0; i < 4; i++) {
            int m3 = i >> 1, m2 = i & 1;
            Qhi[i] = cmul(((m3 ^ t0) ? U[8][2] : U[8][0]),
                          (m2 ? U[9][2] : U[9][0]));
            int m1 = i >> 1, m0 = i & 1;
            Qlo[i] = cmul((m1 ? U[10][2] : U[10][0]),
                          (m0 ? U[11][2] : U[11][0]));
        }
        #pragma unroll
        for (int k = 0; k < 16; k++) {
            const int k0 = k & 1, k1 = (k >> 1) & 1, k2 = (k >> 2) & 1, k3 = k >> 3;
            const int m3 = k3, m2 = k2 ^ k3, m1 = k1 ^ k2, m0 = k0 ^ k1;
            a[k] = cmul(baseG[k0], cmul(Qhi[(m3 << 1) | m2], Qlo[(m1 << 1) | m0]));
        }
    }

    // ===== layers 1,2 =====
    #pragma unroll
    for (int layer = 1; layer < 3; layer++) {
        // A-phase shfl: wires 4..7 on lane bit (7-w)
        #pragma unroll
        for (int w = 4; w < 8; w++) {
            const int lb = 7 - w;
            float2 u00 = U[w][0], u01 = U[w][1], u10 = U[w][2], u11 = U[w][3];
            bool hi = (lane >> lb) & 1;
            float2 ca = hi ? u11 : u00;
            float2 cb = hi ? u10 : u01;
            #pragma unroll
            for (int k = 0; k < 16; k++) {
                float2 p = shflx(a[k], 1 << lb);
                a[k] = cfma2(ca, a[k], cb, p);
            }
        }
        // A-phase reg: wires 8..11 on k bit (11-w)
        #pragma unroll
        for (int w = 8; w < 12; w++) {
            const int bp = 11 - w;
            float2 u00 = U[w][0], u01 = U[w][1], u10 = U[w][2], u11 = U[w][3];
            #pragma unroll
            for (int k0 = 0; k0 < 16; k0++) {
                if (k0 & (1 << bp)) continue;
                const int k1 = k0 | (1 << bp);
                float2 a0 = a[k0], a1 = a[k1];
                a[k0] = cfma2(u00, a0, u01, a1);
                a[k1] = cfma2(u10, a0, u11, a1);
            }
        }

        // transpose A -> B (f4 write on A side, f2 read on B side)
        __syncthreads();
        #pragma unroll
        for (int p = 0; p < 8; p++)
            st4[(tid << 3) | (p ^ t3)] =
                make_float4(a[2*p].x, a[2*p].y, a[2*p+1].x, a[2*p+1].y);
        __syncthreads();
        #pragma unroll
        for (int k = 0; k < 16; k++)
            a[k] = st[(k << 8) | tB];

        // B-phase reg: wires 0..3 on k bit (3-w)
        #pragma unroll
        for (int w = 0; w < 4; w++) {
            const int bp = 3 - w;
            float2 u00 = U[w][0], u01 = U[w][1], u10 = U[w][2], u11 = U[w][3];
            #pragma unroll
            for (int k0 = 0; k0 < 16; k0++) {
                if (k0 & (1 << bp)) continue;
                const int k1 = k0 | (1 << bp);
                float2 a0 = a[k0], a1 = a[k1];
                a[k0] = cfma2(u00, a0, u01, a1);
                a[k1] = cfma2(u10, a0, u11, a1);
            }
        }

        if (layer == 1) {
            // fused CNOT-ring perm back to mapping A (f2 write, f4 read)
            __syncthreads();
            #pragma unroll
            for (int k = 0; k < 16; k++)
                st[PLtid ^ PK.v[k]] = a[k];
            __syncthreads();
            #pragma unroll
            for (int p = 0; p < 8; p++) {
                float4 v = st4[(tid << 3) | (p ^ t3)];
                a[2*p]   = make_float2(v.x, v.y);
                a[2*p+1] = make_float2(v.z, v.w);
            }
        }
    }

    // ===== Z expectations in mapping B, final perm folded into signs =====
    // k-signatures: A=k0^k1^k2 (w0), B=k2^k3 (w1), C=k1^k2^k3 (w2), D=k0^k1^k2^k3 (w>=3)
    float SA = 0.f, SB = 0.f, SC = 0.f, SD = 0.f;
    #pragma unroll
    for (int k = 0; k < 16; k++) {
        float pr = a[k].x * a[k].x + a[k].y * a[k].y;
        const int k0 = k & 1, k1 = (k >> 1) & 1, k2 = (k >> 2) & 1, k3 = k >> 3;
        SA += (k0 ^ k1 ^ k2)      ? -pr : pr;
        SB += (k2 ^ k3)           ? -pr : pr;
        SC += (k1 ^ k2 ^ k3)      ? -pr : pr;
        SD += (k0 ^ k1 ^ k2 ^ k3) ? -pr : pr;
    }
    float zl[NQ];
    {
        const int ptid = __popc(tid) & 1;
        zl[0] = ptid ? -SA : SA;
        zl[1] = SB;
        zl[2] = SC;
        zl[3] = SD;
        #pragma unroll
        for (int w = 4; w < 12; w++) {
            const int j = 11 - w;
            zl[w] = (__popc(tid >> j) & 1) ? -SD : SD;
        }
    }

    #pragma unroll
    for (int w = 0; w < NQ; w++) {
        #pragma unroll
        for (int off = 16; off > 0; off >>= 1)
            zl[w] += __shfl_xor_sync(0xFFFFFFFFu, zl[w], off);
    }
    if (lane == 0) {
        #pragma unroll
        for (int w = 0; w < NQ; w++) zred[w][warp] = zl[w];
    }
    __syncthreads();
    if (tid < NQ) {
        float z = 0.f;
        #pragma unroll
        for (int j = 0; j < BLK / 32; j++) z += zred[tid][j];
        zfin[tid] = z;
    }
    __syncthreads();

    // ---- MLP: relu(z @ w1^T + b1) @ w2^T + b2 ----
    if (tid < HID) {
        float h = b1[tid];
        #pragma unroll
        for (int i = 0; i < NQ; i++) h += zfin[i] * w1[tid * NQ + i];
        hbuf[tid] = fmaxf(h, 0.f);
    }
    __syncthreads();
    float o = b2[tid];
    #pragma unroll
    for (int j = 0; j < HID; j++) o += hbuf[j] * w2[tid * HID + j];
    out[b * OUTDIM + tid] = o;
}

extern "C" void kernel_launch(void* const* d_in, const int* in_sizes, int n_in,
                              void* d_out, int out_size) {
    const float* x  = (const float*)d_in[0];
    const float* rw = (const float*)d_in[1];
    const float* rb = (const float*)d_in[2];
    const float* w1 = (const float*)d_in[3];
    const float* b1 = (const float*)d_in[4];
    const float* w2 = (const float*)d_in[5];
    const float* b2 = (const float*)d_in[6];
    float* out = (float*)d_out;
    int batch = in_sizes[0] / 48;
    quantum_reupload_kernel<<<batch, BLK>>>(x, rw, rb, w1, b1, w2, b2, out);
}

// round 10
// speedup vs baseline: 3.5082x; 2.1744x over previous
#include <cuda_runtime.h>
#include <cuda_bf16.h>

#define NQ        12
#define BLK       256
#define OUTDIM    256
#define HID       64

__device__ __forceinline__ float2 cmul(float2 a, float2 b) {
    return make_float2(a.x * b.x - a.y * b.y, a.x * b.y + a.y * b.x);
}

__device__ __forceinline__ float2 cfma2(float2 ca, float2 a, float2 cb, float2 b) {
    float2 n;
    n.x = ca.x * a.x - ca.y * a.y + cb.x * b.x - cb.y * b.y;
    n.y = ca.x * a.y + ca.y * a.x + cb.x * b.y + cb.y * b.x;
    return n;
}

__device__ __forceinline__ float2 shflx(float2 v, int m) {
    float2 r;
    r.x = __shfl_xor_sync(0xFFFFFFFFu, v.x, m);
    r.y = __shfl_xor_sync(0xFFFFFFFFu, v.y, m);
    return r;
}

// CNOT-ring composite: out bit p (p<=10) = XOR of in bits p..11; bit 11 = XOR of bits 0..10.
__host__ __device__ constexpr int Lmap(int b) {
    int r = 0;
    for (int p = 0; p <= 10; p++) {
        int par = 0;
        for (int q = p; q <= 11; q++) par ^= (b >> q) & 1;
        r |= par << p;
    }
    int par = 0;
    for (int q = 0; q <= 10; q++) par ^= (b >> q) & 1;
    return r | (par << 11);
}
// bit-0-preserving swizzle: xor addr bits 3:1 with addr bits 6:4
__host__ __device__ constexpr int swzB(int x) { return x ^ (((x >> 4) & 7) << 1); }
struct PKt { int v[16]; };
__host__ __device__ constexpr PKt mkPK() {
    PKt t{};
    for (int k = 0; k < 16; k++) t.v[k] = swzB(Lmap(k << 8));
    return t;
}

__global__ __launch_bounds__(BLK, 4) void quantum_reupload_kernel(
    const float* __restrict__ x,    // [B, 48]
    const float* __restrict__ rw,   // [12, 3, 4]
    const float* __restrict__ rb,   // [12, 3]
    const float* __restrict__ w1,   // [64, 12]
    const float* __restrict__ b1,   // [64]
    const float* __restrict__ w2,   // [256, 64]
    const float* __restrict__ b2,   // [256]
    float* __restrict__ out)        // [B, 256]
{
    __shared__ __align__(16) float2 st[4096];   // 32 KB exchange buffer
    __shared__ float2 U[NQ][4];
    __shared__ float  zred[NQ][BLK/32];
    __shared__ float  zfin[NQ];
    __shared__ __align__(16) float hbuf[HID];

    const int b    = blockIdx.x;
    const int tid  = threadIdx.x;       // 0..255
    const int lane = tid & 31;
    const int warp = tid >> 5;

    constexpr PKt PK = mkPK();          // swzB(L(k<<8)) constants

    // ---- per-batch U3 matrices (layer-invariant) ----
    if (tid < NQ) {
        const float* xb  = x  + b * 48 + tid * 4;
        const float* rwi = rw + tid * 12;
        const float* rbi = rb + tid * 3;
        float x0 = xb[0], x1 = xb[1], x2 = xb[2], x3 = xb[3];
        float th = rbi[0] + rwi[0]*x0 + rwi[1]*x1 + rwi[2] *x2 + rwi[3] *x3;
        float ph = rbi[1] + rwi[4]*x0 + rwi[5]*x1 + rwi[6] *x2 + rwi[7] *x3;
        float lm = rbi[2] + rwi[8]*x0 + rwi[9]*x1 + rwi[10]*x2 + rwi[11]*x3;
        float sh, ch, sp, cp, sl, cl;
        sincosf(th * 0.5f, &sh, &ch);
        sincosf(ph,        &sp, &cp);
        sincosf(lm,        &sl, &cl);
        U[tid][0] = make_float2(ch, 0.f);
        U[tid][1] = make_float2(-cl * sh, -sl * sh);
        U[tid][2] = make_float2( cp * sh,  sp * sh);
        U[tid][3] = make_float2((cp*cl - sp*sl) * ch, (cp*sl + sp*cl) * ch);
    }
    __syncthreads();

    // L(tid part) via suffix parity over 8 bits + bit 11 = parity(tid)
    int y = tid; y ^= y >> 1; y ^= y >> 2; y ^= y >> 4;
    const int Ltid  = (y & 0xFF) | ((y & 1) << 11);
    const int PLtid = swzB(Ltid);
    const int t3    = tid & 7;                          // A-side f4 slot xor key
    const int tB    = tid ^ (((tid >> 4) & 7) << 1);    // B-read addr part

    const int t0 = tid & 1, t1 = (tid >> 1) & 1, t2 = (tid >> 2) & 1,
              t3b = (tid >> 3) & 1, t4 = (tid >> 4) & 1, t5 = (tid >> 5) & 1,
              t6 = (tid >> 6) & 1, t7 = (tid >> 7) & 1;

    float2 a[16];
    float4* st4 = (float4*)st;

    // ===== direct build of (perm ∘ layer-0-U3) state in mapping A =====
    {
        float2 base =      (t5 ^ t6) ? U[2][2] : U[2][0];
        base = cmul(base, ((t4 ^ t5) ? U[3][2] : U[3][0]));
        base = cmul(base, ((t3b ^ t4) ? U[4][2] : U[4][0]));
        base = cmul(base, ((t2 ^ t3b) ? U[5][2] : U[5][0]));
        base = cmul(base, ((t1 ^ t2) ? U[6][2] : U[6][0]));
        base = cmul(base, ((t0 ^ t1) ? U[7][2] : U[7][0]));
        float2 baseG[2];
        #pragma unroll
        for (int k0 = 0; k0 < 2; k0++) {
            float2 g = cmul(((k0 ^ t7) ? U[0][2] : U[0][0]),
                            ((k0 ^ t6 ^ t7) ? U[1][2] : U[1][0]));
            baseG[k0] = cmul(base, g);
        }
        float2 Qhi[4], Qlo[4];
        #pragma unroll
        for (int i = 0; i < 4; i++) {
            int m3 = i >> 1, m2 = i & 1;
            Qhi[i] = cmul(((m3 ^ t0) ? U[8][2] : U[8][0]),
                          (m2 ? U[9][2] : U[9][0]));
            int m1 = i >> 1, m0 = i & 1;
            Qlo[i] = cmul((m1 ? U[10][2] : U[10][0]),
                          (m0 ? U[11][2] : U[11][0]));
        }
        #pragma unroll
        for (int k = 0; k < 16; k++) {
            const int k0 = k & 1, k1 = (k >> 1) & 1, k2 = (k >> 2) & 1, k3 = k >> 3;
            const int m3 = k3, m2 = k2 ^ k3, m1 = k1 ^ k2, m0 = k0 ^ k1;
            a[k] = cmul(baseG[k0], cmul(Qhi[(m3 << 1) | m2], Qlo[(m1 << 1) | m0]));
        }
    }

    // ===== layers 1,2 =====
    #pragma unroll
    for (int layer = 1; layer < 3; layer++) {
        // A-phase shfl: wires 4..7 on lane bit (7-w)
        #pragma unroll
        for (int w = 4; w < 8; w++) {
            const int lb = 7 - w;
            float2 u00 = U[w][0], u01 = U[w][1], u10 = U[w][2], u11 = U[w][3];
            bool hi = (lane >> lb) & 1;
            float2 ca = hi ? u11 : u00;
            float2 cb = hi ? u10 : u01;
            #pragma unroll
            for (int k = 0; k < 16; k++) {
                float2 p = shflx(a[k], 1 << lb);
                a[k] = cfma2(ca, a[k], cb, p);
            }
        }
        // A-phase reg: wires 8..11 on k bit (11-w)
        #pragma unroll
        for (int w = 8; w < 12; w++) {
            const int bp = 11 - w;
            float2 u00 = U[w][0], u01 = U[w][1], u10 = U[w][2], u11 = U[w][3];
            #pragma unroll
            for (int k0 = 0; k0 < 16; k0++) {
                if (k0 & (1 << bp)) continue;
                const int k1 = k0 | (1 << bp);
                float2 a0 = a[k0], a1 = a[k1];
                a[k0] = cfma2(u00, a0, u01, a1);
                a[k1] = cfma2(u10, a0, u11, a1);
            }
        }

        // transpose A -> B (f4 write on A side, f2 read on B side)
        __syncthreads();
        #pragma unroll
        for (int p = 0; p < 8; p++)
            st4[(tid << 3) | (p ^ t3)] =
                make_float4(a[2*p].x, a[2*p].y, a[2*p+1].x, a[2*p+1].y);
        __syncthreads();
        #pragma unroll
        for (int k = 0; k < 16; k++)
            a[k] = st[(k << 8) | tB];

        // B-phase reg: wires 0..3 on k bit (3-w)
        #pragma unroll
        for (int w = 0; w < 4; w++) {
            const int bp = 3 - w;
            float2 u00 = U[w][0], u01 = U[w][1], u10 = U[w][2], u11 = U[w][3];
            #pragma unroll
            for (int k0 = 0; k0 < 16; k0++) {
                if (k0 & (1 << bp)) continue;
                const int k1 = k0 | (1 << bp);
                float2 a0 = a[k0], a1 = a[k1];
                a[k0] = cfma2(u00, a0, u01, a1);
                a[k1] = cfma2(u10, a0, u11, a1);
            }
        }

        if (layer == 1) {
            // fused CNOT-ring perm back to mapping A (f2 write, f4 read)
            __syncthreads();
            #pragma unroll
            for (int k = 0; k < 16; k++)
                st[PLtid ^ PK.v[k]] = a[k];
            __syncthreads();
            #pragma unroll
            for (int p = 0; p < 8; p++) {
                float4 v = st4[(tid << 3) | (p ^ t3)];
                a[2*p]   = make_float2(v.x, v.y);
                a[2*p+1] = make_float2(v.z, v.w);
            }
        }
    }

    // ===== Z expectations in mapping B, final perm folded into signs =====
    float SA = 0.f, SB = 0.f, SC = 0.f, SD = 0.f;
    #pragma unroll
    for (int k = 0; k < 16; k++) {
        float pr = a[k].x * a[k].x + a[k].y * a[k].y;
        const int k0 = k & 1, k1 = (k >> 1) & 1, k2 = (k >> 2) & 1, k3 = k >> 3;
        SA += (k0 ^ k1 ^ k2)      ? -pr : pr;
        SB += (k2 ^ k3)           ? -pr : pr;
        SC += (k1 ^ k2 ^ k3)      ? -pr : pr;
        SD += (k0 ^ k1 ^ k2 ^ k3) ? -pr : pr;
    }
    float zl[NQ];
    {
        const int ptid = __popc(tid) & 1;
        zl[0] = ptid ? -SA : SA;
        zl[1] = SB;
        zl[2] = SC;
        zl[3] = SD;
        #pragma unroll
        for (int w = 4; w < 12; w++) {
            const int j = 11 - w;
            zl[w] = (__popc(tid >> j) & 1) ? -SD : SD;
        }
    }

    #pragma unroll
    for (int w = 0; w < NQ; w++) {
        #pragma unroll
        for (int off = 16; off > 0; off >>= 1)
            zl[w] += __shfl_xor_sync(0xFFFFFFFFu, zl[w], off);
    }
    if (lane == 0) {
        #pragma unroll
        for (int w = 0; w < NQ; w++) zred[w][warp] = zl[w];
    }
    __syncthreads();
    if (tid < NQ) {
        float z = 0.f;
        #pragma unroll
        for (int j = 0; j < BLK / 32; j++) z += zred[tid][j];
        zfin[tid] = z;
    }
    __syncthreads();

    // ---- MLP layer 1: h = relu(z @ w1^T + b1) ----
    if (tid < HID) {
        float h = b1[tid];
        #pragma unroll
        for (int i = 0; i < NQ; i++) h += zfin[i] * w1[tid * NQ + i];
        hbuf[tid] = fmaxf(h, 0.f);
    }
    __syncthreads();

    // ---- MLP layer 2, warp-cooperative coalesced GEMV ----
    // warp handles rows [warp*32, warp*32+32). Per round, lanes 0-15 do row
    // (base+2r), lanes 16-31 do row (base+2r+1): LDG.128 fully coalesced.
    {
        float* ob = (float*)st;             // 256-float output staging (st is free)
        const int half = lane >> 4;         // 0 or 1
        const int l16  = lane & 15;
        const float4 hv = ((const float4*)hbuf)[l16];
        #pragma unroll
        for (int r = 0; r < 16; r++) {
            const int row = warp * 32 + r * 2 + half;
            float4 wv = *(const float4*)(w2 + row * HID + l16 * 4);
            float s = wv.x * hv.x + wv.y * hv.y + wv.z * hv.z + wv.w * hv.w;
            s += __shfl_xor_sync(0xFFFFFFFFu, s, 1);
            s += __shfl_xor_sync(0xFFFFFFFFu, s, 2);
            s += __shfl_xor_sync(0xFFFFFFFFu, s, 4);
            s += __shfl_xor_sync(0xFFFFFFFFu, s, 8);
            if (l16 == 0) ob[row] = s;
        }
        __syncthreads();
        out[b * OUTDIM + tid] = ob[tid] + b2[tid];   // coalesced
    }
}

extern "C" void kernel_launch(void* const* d_in, const int* in_sizes, int n_in,
                              void* d_out, int out_size) {
    const float* x  = (const float*)d_in[0];
    const float* rw = (const float*)d_in[1];
    const float* rb = (const float*)d_in[2];
    const float* w1 = (const float*)d_in[3];
    const float* b1 = (const float*)d_in[4];
    const float* w2 = (const float*)d_in[5];
    const float* b2 = (const float*)d_in[6];
    float* out = (float*)d_out;
    int batch = in_sizes[0] / 48;
    quantum_reupload_kernel<<<batch, BLK>>>(x, rw, rb, w1, b1, w2, b2, out);
}

// round 11
// speedup vs baseline: 3.6424x; 1.0383x over previous
#include <cuda_runtime.h>
#include <cuda_bf16.h>

#define NQ        12
#define BLK       256
#define OUTDIM    256
#define HID       64

typedef unsigned long long ull;

__device__ __forceinline__ float2 cmul(float2 a, float2 b) {
    return make_float2(a.x * b.x - a.y * b.y, a.x * b.y + a.y * b.x);
}

// ---- packed f32x2 helpers (FFMA2 path, PTX-only) ----
__device__ __forceinline__ ull pk2(float lo, float hi) {
    ull r;
    asm("mov.b64 %0, {%1, %2};" : "=l"(r) : "f"(lo), "f"(hi));
    return r;
}
__device__ __forceinline__ float2 unpk(ull v) {
    float lo, hi;
    asm("mov.b64 {%0, %1}, %2;" : "=f"(lo), "=f"(hi) : "l"(v));
    return make_float2(lo, hi);
}
__device__ __forceinline__ ull swp(ull v) {
    ull r;
    asm("{\n\t.reg .b32 lo, hi;\n\tmov.b64 {lo, hi}, %1;\n\tmov.b64 %0, {hi, lo};\n\t}"
        : "=l"(r) : "l"(v));
    return r;
}
__device__ __forceinline__ ull fma2p(ull a, ull b, ull c) {
    ull r;
    asm("fma.rn.f32x2 %0, %1, %2, %3;" : "=l"(r) : "l"(a), "l"(b), "l"(c));
    return r;
}
__device__ __forceinline__ ull mul2p(ull a, ull b) {
    ull r;
    asm("mul.rn.f32x2 %0, %1, %2;" : "=l"(r) : "l"(a), "l"(b));
    return r;
}

// complex butterfly on packed amps: (a0,a1) <- U * (a0,a1)
// c = [u00x2,u00yn2, u01x2,u01yn2, u10x2,u10yn2, u11x2,u11yn2]
__device__ __forceinline__ void bfly(ull& a0, ull& a1,
                                     ull c0, ull c1, ull c2, ull c3,
                                     ull c4, ull c5, ull c6, ull c7) {
    ull s0 = swp(a0), s1 = swp(a1);
    ull n0 = fma2p(c0, a0, fma2p(c1, s0, fma2p(c2, a1, mul2p(c3, s1))));
    ull n1 = fma2p(c4, a0, fma2p(c5, s0, fma2p(c6, a1, mul2p(c7, s1))));
    a0 = n0; a1 = n1;
}

// CNOT-ring composite: out bit p (p<=10) = XOR of in bits p..11; bit 11 = XOR of bits 0..10.
__host__ __device__ constexpr int Lmap(int b) {
    int r = 0;
    for (int p = 0; p <= 10; p++) {
        int par = 0;
        for (int q = p; q <= 11; q++) par ^= (b >> q) & 1;
        r |= par << p;
    }
    int par = 0;
    for (int q = 0; q <= 10; q++) par ^= (b >> q) & 1;
    return r | (par << 11);
}
__host__ __device__ constexpr int swzB(int x) { return x ^ (((x >> 4) & 7) << 1); }
struct PKt { int v[16]; };
__host__ __device__ constexpr PKt mkPK() {
    PKt t{};
    for (int k = 0; k < 16; k++) t.v[k] = swzB(Lmap(k << 8));
    return t;
}

__global__ __launch_bounds__(BLK) void quantum_reupload_kernel(
    const float* __restrict__ x,    // [B, 48]
    const float* __restrict__ rw,   // [12, 3, 4]
    const float* __restrict__ rb,   // [12, 3]
    const float* __restrict__ w1,   // [64, 12]
    const float* __restrict__ b1,   // [64]
    const float* __restrict__ w2,   // [256, 64]
    const float* __restrict__ b2,   // [256]
    float* __restrict__ out)        // [B, 256]
{
    __shared__ __align__(16) float2 st[4096];   // 32 KB exchange buffer
    __shared__ float2 U[NQ][4];
    __shared__ ull    Upk[NQ][8];               // packed gate coeffs
    __shared__ float  zred[NQ][BLK/32];
    __shared__ float  zfin[NQ];
    __shared__ __align__(16) float hbuf[HID];

    const int b    = blockIdx.x;
    const int tid  = threadIdx.x;       // 0..255
    const int lane = tid & 31;
    const int warp = tid >> 5;

    constexpr PKt PK = mkPK();          // swzB(L(k<<8)) constants

    // ---- per-batch U3 matrices (layer-invariant) ----
    if (tid < NQ) {
        const float* xb  = x  + b * 48 + tid * 4;
        const float* rwi = rw + tid * 12;
        const float* rbi = rb + tid * 3;
        float x0 = xb[0], x1 = xb[1], x2 = xb[2], x3 = xb[3];
        float th = rbi[0] + rwi[0]*x0 + rwi[1]*x1 + rwi[2] *x2 + rwi[3] *x3;
        float ph = rbi[1] + rwi[4]*x0 + rwi[5]*x1 + rwi[6] *x2 + rwi[7] *x3;
        float lm = rbi[2] + rwi[8]*x0 + rwi[9]*x1 + rwi[10]*x2 + rwi[11]*x3;
        float sh, ch, sp, cp, sl, cl;
        sincosf(th * 0.5f, &sh, &ch);
        sincosf(ph,        &sp, &cp);
        sincosf(lm,        &sl, &cl);
        float2 u00 = make_float2(ch, 0.f);
        float2 u01 = make_float2(-cl * sh, -sl * sh);
        float2 u10 = make_float2( cp * sh,  sp * sh);
        float2 u11 = make_float2((cp*cl - sp*sl) * ch, (cp*sl + sp*cl) * ch);
        U[tid][0] = u00; U[tid][1] = u01; U[tid][2] = u10; U[tid][3] = u11;
        Upk[tid][0] = pk2(u00.x, u00.x); Upk[tid][1] = pk2(-u00.y, u00.y);
        Upk[tid][2] = pk2(u01.x, u01.x); Upk[tid][3] = pk2(-u01.y, u01.y);
        Upk[tid][4] = pk2(u10.x, u10.x); Upk[tid][5] = pk2(-u10.y, u10.y);
        Upk[tid][6] = pk2(u11.x, u11.x); Upk[tid][7] = pk2(-u11.y, u11.y);
    }
    __syncthreads();

    // L(tid part) via suffix parity over 8 bits + bit 11 = parity(tid)
    int y = tid; y ^= y >> 1; y ^= y >> 2; y ^= y >> 4;
    const int Ltid  = (y & 0xFF) | ((y & 1) << 11);
    const int PLtid = swzB(Ltid);
    const int t3    = tid & 7;                          // A-side f4 slot xor key
    const int tB    = tid ^ (((tid >> 4) & 7) << 1);    // B-read addr part

    const int t0 = tid & 1, t1 = (tid >> 1) & 1, t2 = (tid >> 2) & 1,
              t3b = (tid >> 3) & 1, t4 = (tid >> 4) & 1, t5 = (tid >> 5) & 1,
              t6 = (tid >> 6) & 1, t7 = (tid >> 7) & 1;

    ull A[16];
    ull*        stu = (ull*)st;
    ulonglong2* st2 = (ulonglong2*)st;

    // ===== direct build of (perm ∘ layer-0-U3) state in mapping A (scalar) =====
    {
        float2 base =      (t5 ^ t6) ? U[2][2] : U[2][0];
        base = cmul(base, ((t4 ^ t5) ? U[3][2] : U[3][0]));
        base = cmul(base, ((t3b ^ t4) ? U[4][2] : U[4][0]));
        base = cmul(base, ((t2 ^ t3b) ? U[5][2] : U[5][0]));
        base = cmul(base, ((t1 ^ t2) ? U[6][2] : U[6][0]));
        base = cmul(base, ((t0 ^ t1) ? U[7][2] : U[7][0]));
        float2 baseG[2];
        #pragma unroll
        for (int k0 = 0; k0 < 2; k0++) {
            float2 g = cmul(((k0 ^ t7) ? U[0][2] : U[0][0]),
                            ((k0 ^ t6 ^ t7) ? U[1][2] : U[1][0]));
            baseG[k0] = cmul(base, g);
        }
        float2 Qhi[4], Qlo[4];
        #pragma unroll
        for (int i = 0; i < 4; i++) {
            int m3 = i >> 1, m2 = i & 1;
            Qhi[i] = cmul(((m3 ^ t0) ? U[8][2] : U[8][0]),
                          (m2 ? U[9][2] : U[9][0]));
            int m1 = i >> 1, m0 = i & 1;
            Qlo[i] = cmul((m1 ? U[10][2] : U[10][0]),
                          (m0 ? U[11][2] : U[11][0]));
        }
        #pragma unroll
        for (int k = 0; k < 16; k++) {
            const int k0 = k & 1, k1 = (k >> 1) & 1, k2 = (k >> 2) & 1, k3 = k >> 3;
            const int m3 = k3, m2 = k2 ^ k3, m1 = k1 ^ k2, m0 = k0 ^ k1;
            float2 v = cmul(baseG[k0], cmul(Qhi[(m3 << 1) | m2], Qlo[(m1 << 1) | m0]));
            A[k] = pk2(v.x, v.y);
        }
    }

    // ===== layers 1,2 =====
    #pragma unroll
    for (int layer = 1; layer < 3; layer++) {
        // A-phase shfl: wires 4..7 on lane bit (7-w)
        #pragma unroll
        for (int w = 4; w < 8; w++) {
            const int lb = 7 - w;
            const bool hi = (lane >> lb) & 1;
            const ull cax = hi ? Upk[w][6] : Upk[w][0];
            const ull cay = hi ? Upk[w][7] : Upk[w][1];
            const ull cbx = hi ? Upk[w][4] : Upk[w][2];
            const ull cby = hi ? Upk[w][5] : Upk[w][3];
            #pragma unroll
            for (int k = 0; k < 16; k++) {
                ull p  = __shfl_xor_sync(0xFFFFFFFFu, A[k], 1 << lb);
                ull sa = swp(A[k]), sp_ = swp(p);
                A[k] = fma2p(cax, A[k], fma2p(cay, sa, fma2p(cbx, p, mul2p(cby, sp_))));
            }
        }
        // A-phase reg: wires 8..11 on k bit (11-w)
        #pragma unroll
        for (int w = 8; w < 12; w++) {
            const int bp = 11 - w;
            const ull c0 = Upk[w][0], c1 = Upk[w][1], c2 = Upk[w][2], c3 = Upk[w][3],
                      c4 = Upk[w][4], c5 = Upk[w][5], c6 = Upk[w][6], c7 = Upk[w][7];
            #pragma unroll
            for (int k0 = 0; k0 < 16; k0++) {
                if (k0 & (1 << bp)) continue;
                const int k1 = k0 | (1 << bp);
                bfly(A[k0], A[k1], c0, c1, c2, c3, c4, c5, c6, c7);
            }
        }

        // transpose A -> B (128-bit write on A side, 64-bit read on B side)
        __syncthreads();
        #pragma unroll
        for (int p = 0; p < 8; p++)
            st2[(tid << 3) | (p ^ t3)] = make_ulonglong2(A[2*p], A[2*p+1]);
        __syncthreads();
        #pragma unroll
        for (int k = 0; k < 16; k++)
            A[k] = stu[(k << 8) | tB];

        // B-phase reg: wires 0..3 on k bit (3-w)
        #pragma unroll
        for (int w = 0; w < 4; w++) {
            const int bp = 3 - w;
            const ull c0 = Upk[w][0], c1 = Upk[w][1], c2 = Upk[w][2], c3 = Upk[w][3],
                      c4 = Upk[w][4], c5 = Upk[w][5], c6 = Upk[w][6], c7 = Upk[w][7];
            #pragma unroll
            for (int k0 = 0; k0 < 16; k0++) {
                if (k0 & (1 << bp)) continue;
                const int k1 = k0 | (1 << bp);
                bfly(A[k0], A[k1], c0, c1, c2, c3, c4, c5, c6, c7);
            }
        }

        if (layer == 1) {
            // fused CNOT-ring perm back to mapping A (64-bit write, 128-bit read)
            __syncthreads();
            #pragma unroll
            for (int k = 0; k < 16; k++)
                stu[PLtid ^ PK.v[k]] = A[k];
            __syncthreads();
            #pragma unroll
            for (int p = 0; p < 8; p++) {
                ulonglong2 v = st2[(tid << 3) | (p ^ t3)];
                A[2*p]   = v.x;
                A[2*p+1] = v.y;
            }
        }
    }

    // ===== Z expectations in mapping B, final perm folded into signs =====
    float SA = 0.f, SB = 0.f, SC = 0.f, SD = 0.f;
    #pragma unroll
    for (int k = 0; k < 16; k++) {
        float2 v = unpk(A[k]);
        float pr = v.x * v.x + v.y * v.y;
        const int k0 = k & 1, k1 = (k >> 1) & 1, k2 = (k >> 2) & 1, k3 = k >> 3;
        SA += (k0 ^ k1 ^ k2)      ? -pr : pr;
        SB += (k2 ^ k3)           ? -pr : pr;
        SC += (k1 ^ k2 ^ k3)      ? -pr : pr;
        SD += (k0 ^ k1 ^ k2 ^ k3) ? -pr : pr;
    }
    float zl[NQ];
    {
        const int ptid = __popc(tid) & 1;
        zl[0] = ptid ? -SA : SA;
        zl[1] = SB;
        zl[2] = SC;
        zl[3] = SD;
        #pragma unroll
        for (int w = 4; w < 12; w++) {
            const int j = 11 - w;
            zl[w] = (__popc(tid >> j) & 1) ? -SD : SD;
        }
    }

    #pragma unroll
    for (int w = 0; w < NQ; w++) {
        #pragma unroll
        for (int off = 16; off > 0; off >>= 1)
            zl[w] += __shfl_xor_sync(0xFFFFFFFFu, zl[w], off);
    }
    if (lane == 0) {
        #pragma unroll
        for (int w = 0; w < NQ; w++) zred[w][warp] = zl[w];
    }
    __syncthreads();
    if (tid < NQ) {
        float z = 0.f;
        #pragma unroll
        for (int j = 0; j < BLK / 32; j++) z += zred[tid][j];
        zfin[tid] = z;
    }
    __syncthreads();

    // ---- MLP layer 1: h = relu(z @ w1^T + b1) ----
    if (tid < HID) {
        float h = b1[tid];
        #pragma unroll
        for (int i = 0; i < NQ; i++) h += zfin[i] * w1[tid * NQ + i];
        hbuf[tid] = fmaxf(h, 0.f);
    }
    __syncthreads();

    // ---- MLP layer 2, warp-cooperative coalesced GEMV ----
    {
        float* ob = (float*)st;
        const int half = lane >> 4;
        const int l16  = lane & 15;
        const float4 hv = ((const float4*)hbuf)[l16];
        #pragma unroll
        for (int r = 0; r < 16; r++) {
            const int row = warp * 32 + r * 2 + half;
            float4 wv = *(const float4*)(w2 + row * HID + l16 * 4);
            float s = wv.x * hv.x + wv.y * hv.y + wv.z * hv.z + wv.w * hv.w;
            s += __shfl_xor_sync(0xFFFFFFFFu, s, 1);
            s += __shfl_xor_sync(0xFFFFFFFFu, s, 2);
            s += __shfl_xor_sync(0xFFFFFFFFu, s, 4);
            s += __shfl_xor_sync(0xFFFFFFFFu, s, 8);
            if (l16 == 0) ob[row] = s;
        }
        __syncthreads();
        out[b * OUTDIM + tid] = ob[tid] + b2[tid];
    }
}

extern "C" void kernel_launch(void* const* d_in, const int* in_sizes, int n_in,
                              void* d_out, int out_size) {
    const float* x  = (const float*)d_in[0];
    const float* rw = (const float*)d_in[1];
    const float* rb = (const float*)d_in[2];
    const float* w1 = (const float*)d_in[3];
    const float* b1 = (const float*)d_in[4];
    const float* w2 = (const float*)d_in[5];
    const float* b2 = (const float*)d_in[6];
    float* out = (float*)d_out;
    int batch = in_sizes[0] / 48;
    quantum_reupload_kernel<<<batch, BLK>>>(x, rw, rb, w1, b1, w2, b2, out);
}

// round 12
// speedup vs baseline: 4.8395x; 1.3286x over previous
#include <cuda_runtime.h>
#include <cuda_bf16.h>

#define NQ        12
#define BLK       256
#define OUTDIM    256
#define HID       64

typedef unsigned long long ull;

__device__ __forceinline__ float2 cmul(float2 a, float2 b) {
    return make_float2(a.x * b.x - a.y * b.y, a.x * b.y + a.y * b.x);
}
__device__ __forceinline__ float2 cjf(float2 e, int c) {
    return c ? make_float2(e.x, -e.y) : e;
}

// ---- packed f32x2 helpers ----
__device__ __forceinline__ ull pk2(float lo, float hi) {
    ull r; asm("mov.b64 %0, {%1, %2};" : "=l"(r) : "f"(lo), "f"(hi)); return r;
}
__device__ __forceinline__ float2 unpk(ull v) {
    float lo, hi; asm("mov.b64 {%0, %1}, %2;" : "=f"(lo), "=f"(hi) : "l"(v));
    return make_float2(lo, hi);
}
__device__ __forceinline__ ull swp(ull v) {
    ull r;
    asm("{\n\t.reg .b32 lo, hi;\n\tmov.b64 {lo, hi}, %1;\n\tmov.b64 %0, {hi, lo};\n\t}"
        : "=l"(r) : "l"(v));
    return r;
}
__device__ __forceinline__ ull fma2p(ull a, ull b, ull c) {
    ull r; asm("fma.rn.f32x2 %0, %1, %2, %3;" : "=l"(r) : "l"(a), "l"(b), "l"(c));
    return r;
}
__device__ __forceinline__ ull mul2p(ull a, ull b) {
    ull r; asm("mul.rn.f32x2 %0, %1, %2;" : "=l"(r) : "l"(a), "l"(b)); return r;
}
__device__ __forceinline__ ull add2p(ull a, ull b) {
    ull r; asm("add.rn.f32x2 %0, %1, %2;" : "=l"(r) : "l"(a), "l"(b)); return r;
}

// real-rotation butterfly: a0' = c a0 - s a1 ; a1' = s a0 + c a1  (packed complex amps)
__device__ __forceinline__ void bflyr(ull& a0, ull& a1, ull c2, ull s2, ull ns2) {
    ull n0 = fma2p(ns2, a1, mul2p(c2, a0));
    ull n1 = fma2p(c2,  a1, mul2p(s2, a0));
    a0 = n0; a1 = n1;
}

// CNOT-ring composite: out bit p (p<=10) = XOR of in bits p..11; bit 11 = XOR of bits 0..10.
__host__ __device__ constexpr int Lmap(int b) {
    int r = 0;
    for (int p = 0; p <= 10; p++) {
        int par = 0;
        for (int q = p; q <= 11; q++) par ^= (b >> q) & 1;
        r |= par << p;
    }
    int par = 0;
    for (int q = 0; q <= 10; q++) par ^= (b >> q) & 1;
    return r | (par << 11);
}
__host__ __device__ constexpr int swzB(int x) { return x ^ (((x >> 4) & 7) << 1); }
struct PKt { int v[16]; };
__host__ __device__ constexpr PKt mkPK() {
    PKt t{};
    for (int k = 0; k < 16; k++) t.v[k] = swzB(Lmap(k << 8));
    return t;
}

__global__ __launch_bounds__(BLK) void quantum_reupload_kernel(
    const float* __restrict__ x,    // [B, 48]
    const float* __restrict__ rw,   // [12, 3, 4]
    const float* __restrict__ rb,   // [12, 3]
    const float* __restrict__ w1,   // [64, 12]
    const float* __restrict__ b1,   // [64]
    const float* __restrict__ w2,   // [256, 64]
    const float* __restrict__ b2,   // [256]
    float* __restrict__ out)        // [B, 256]
{
    __shared__ __align__(16) float2 st[4096];   // 32 KB exchange buffer
    __shared__ float2 sU10[NQ];                 // U3 col0 lower entry (e^{i phi} s)
    __shared__ float  sCh[NQ], sSh[NQ];         // cos(th/2), sin(th/2)
    __shared__ float2 sEphi[NQ], sElam[NQ];     // e^{i phi}, e^{i lam}
    __shared__ ull    sC2[NQ], sS2[NQ], sNS2[NQ];
    __shared__ float  zred[NQ][BLK/32];
    __shared__ float  zfin[NQ];
    __shared__ __align__(16) float hbuf[HID];

    const int b    = blockIdx.x;
    const int tid  = threadIdx.x;       // 0..255
    const int lane = tid & 31;
    const int warp = tid >> 5;

    constexpr PKt PK = mkPK();          // swzB(L(k<<8)) constants

    // ---- per-batch U3 angles (layer-invariant; params repeat per layer) ----
    if (tid < NQ) {
        const float* xb  = x  + b * 48 + tid * 4;
        const float* rwi = rw + tid * 12;
        const float* rbi = rb + tid * 3;
        float x0 = xb[0], x1 = xb[1], x2 = xb[2], x3 = xb[3];
        float th = rbi[0] + rwi[0]*x0 + rwi[1]*x1 + rwi[2] *x2 + rwi[3] *x3;
        float ph = rbi[1] + rwi[4]*x0 + rwi[5]*x1 + rwi[6] *x2 + rwi[7] *x3;
        float lm = rbi[2] + rwi[8]*x0 + rwi[9]*x1 + rwi[10]*x2 + rwi[11]*x3;
        float sh, ch, sp, cp, sl, cl;
        sincosf(th * 0.5f, &sh, &ch);
        sincosf(ph,        &sp, &cp);
        sincosf(lm,        &sl, &cl);
        sCh[tid]   = ch;  sSh[tid] = sh;
        sU10[tid]  = make_float2(cp * sh, sp * sh);
        sEphi[tid] = make_float2(cp, sp);
        sElam[tid] = make_float2(cl, sl);
        sC2[tid]   = pk2(ch, ch);
        sS2[tid]   = pk2(sh, sh);
        sNS2[tid]  = pk2(-sh, -sh);
    }
    __syncthreads();

    // L(tid part) via suffix parity over 8 bits + bit 11 = parity(tid)
    int y = tid; y ^= y >> 1; y ^= y >> 2; y ^= y >> 4;
    const int Ltid  = (y & 0xFF) | ((y & 1) << 11);
    const int PLtid = swzB(Ltid);
    const int t3    = tid & 7;                          // A-side f4 slot xor key
    const int tB    = tid ^ (((tid >> 4) & 7) << 1);    // B-read addr part

    const int t0 = tid & 1, t1 = (tid >> 1) & 1, t2 = (tid >> 2) & 1,
              t3b = (tid >> 3) & 1, t4 = (tid >> 4) & 1, t5 = (tid >> 5) & 1,
              t6 = (tid >> 6) & 1, t7 = (tid >> 7) & 1;

    ull A[16];
    ull*        stu = (ull*)st;
    ulonglong2* st2 = (ulonglong2*)st;

    auto col0 = [&](int w, int bit) -> float2 {
        return bit ? sU10[w] : make_float2(sCh[w], 0.f);
    };

    // ===== build of (Lam1 ∘ perm ∘ layer-0-U3) state in mapping A =====
    // p=(tid<<4)|k ; x = L^{-1}(p): selectors as validated in R7/R11.
    // Lam1 phase (Sum lam_w * p_{11-w}) folded: tid bits into base chain,
    // k0,k1 into baseG4, k2,k3 into Qhi.
    {
        float2 base = col0(2, t5 ^ t6);
        base = cmul(base, col0(3, t4 ^ t5));
        base = cmul(base, col0(4, t3b ^ t4));
        base = cmul(base, col0(5, t2 ^ t3b));
        base = cmul(base, col0(6, t1 ^ t2));
        base = cmul(base, col0(7, t0 ^ t1));
        // Lam1 thread factors: wire w in 0..7 driven by tid bit t_{7-w}
        if (t7)  base = cmul(base, sElam[0]);
        if (t6)  base = cmul(base, sElam[1]);
        if (t5)  base = cmul(base, sElam[2]);
        if (t4)  base = cmul(base, sElam[3]);
        if (t3b) base = cmul(base, sElam[4]);
        if (t2)  base = cmul(base, sElam[5]);
        if (t1)  base = cmul(base, sElam[6]);
        if (t0)  base = cmul(base, sElam[7]);

        float2 baseG[2];
        #pragma unroll
        for (int k0 = 0; k0 < 2; k0++) {
            float2 g = cmul(col0(0, k0 ^ t7), col0(1, k0 ^ t6 ^ t7));
            baseG[k0] = cmul(base, g);
        }
        // baseG4 over (k0,k1): fold Lam1 k0->elam11, k1->elam10
        float2 bG4[4];
        bG4[0] = baseG[0];
        bG4[1] = cmul(baseG[1], sElam[11]);
        bG4[2] = cmul(baseG[0], sElam[10]);
        bG4[3] = cmul(bG4[1],   sElam[10]);

        float2 Qhi[4], Qlo[4];
        #pragma unroll
        for (int i = 0; i < 4; i++) {
            int m3 = i >> 1, m2 = i & 1;
            Qhi[i] = cmul(col0(8, m3 ^ t0), col0(9, m2));
            int m1 = i >> 1, m0 = i & 1;
            Qlo[i] = cmul(col0(10, m1), col0(11, m0));
        }
        // Lam1 fold on Qhi: (k3? elam8)(k2? elam9), k3=m3, k2=m2^m3
        Qhi[1] = cmul(Qhi[1], sElam[9]);
        Qhi[2] = cmul(Qhi[2], cmul(sElam[8], sElam[9]));
        Qhi[3] = cmul(Qhi[3], sElam[8]);

        #pragma unroll
        for (int k = 0; k < 16; k++) {
            const int k0 = k & 1, k1 = (k >> 1) & 1, k2 = (k >> 2) & 1, k3 = k >> 3;
            const int m3 = k3, m2 = k2 ^ k3, m1 = k1 ^ k2, m0 = k0 ^ k1;
            float2 v = cmul(bG4[k & 3], cmul(Qhi[(m3 << 1) | m2], Qlo[(m1 << 1) | m0]));
            A[k] = pk2(v.x, v.y);
        }
    }

    // ===== G = (Phi1 relabeled by L^{-1}) * Lam2, applied after layer-1 perm =====
    // Build per-thread tables (exact complex products of unit phasors).
    float2 T01g[4], T23v0[4], T23v1[4];
    {
        float2 gt = make_float2(1.f, 0.f);
        // Phi1 thread terms (wires 2..7 on t-XORs)
        if (t5 ^ t6)  gt = cmul(gt, sEphi[2]);
        if (t4 ^ t5)  gt = cmul(gt, sEphi[3]);
        if (t3b ^ t4) gt = cmul(gt, sEphi[4]);
        if (t2 ^ t3b) gt = cmul(gt, sEphi[5]);
        if (t1 ^ t2)  gt = cmul(gt, sEphi[6]);
        if (t0 ^ t1)  gt = cmul(gt, sEphi[7]);
        // Lam2 thread terms (wire w in 0..7 on t_{7-w})
        if (t7)  gt = cmul(gt, sElam[0]);
        if (t6)  gt = cmul(gt, sElam[1]);
        if (t5)  gt = cmul(gt, sElam[2]);
        if (t4)  gt = cmul(gt, sElam[3]);
        if (t3b) gt = cmul(gt, sElam[4]);
        if (t2)  gt = cmul(gt, sElam[5]);
        if (t1)  gt = cmul(gt, sElam[6]);
        if (t0)  gt = cmul(gt, sElam[7]);
        // mixed-term prefactors
        if (t7)       gt = cmul(gt, sEphi[0]);   // (k0^t7) phi0
        if (t6 ^ t7)  gt = cmul(gt, sEphi[1]);   // (k0^t6^t7) phi1
        if (t0)       gt = cmul(gt, sEphi[8]);   // (k3^t0) phi8

        float2 E0 = cmul(sElam[11], cmul(cjf(sEphi[0], t7), cjf(sEphi[1], t6 ^ t7)));
        float2 E1 = sElam[10];
        float2 E2 = sElam[9];
        float2 E3 = cmul(sElam[8], cjf(sEphi[8], t0));
        float2 X01 = sEphi[11], X12 = sEphi[10], X23 = sEphi[9];

        T01g[0] = gt;
        T01g[1] = cmul(gt, cmul(E0, X01));
        T01g[2] = cmul(gt, cmul(E1, X01));
        T01g[3] = cmul(gt, cmul(E0, E1));

        float2 e2x = cmul(E2, X23);       // k2-set base (k2^k3=1)
        float2 e3x = cmul(E3, X23);       // k3-set base
        float2 e23 = cmul(E2, E3);        // both set
        T23v0[0] = make_float2(1.f, 0.f);
        T23v0[1] = cmul(e2x, X12);
        T23v0[2] = e3x;
        T23v0[3] = cmul(e23, X12);
        T23v1[0] = X12;
        T23v1[1] = e2x;
        T23v1[2] = cmul(e3x, X12);
        T23v1[3] = e23;
    }

    // ===== layers 1,2 — real rotations only =====
    #pragma unroll
    for (int layer = 1; layer < 3; layer++) {
        // A-phase shfl: wires 4..7 on lane bit (7-w)
        #pragma unroll
        for (int w = 4; w < 8; w++) {
            const int lb = 7 - w;
            const ull c2  = sC2[w];
            const ull sp2 = ((lane >> lb) & 1) ? sS2[w] : sNS2[w];
            #pragma unroll
            for (int k = 0; k < 16; k++) {
                ull p = __shfl_xor_sync(0xFFFFFFFFu, A[k], 1 << lb);
                A[k] = fma2p(c2, A[k], mul2p(sp2, p));
            }
        }
        // A-phase reg: wires 8..11 on k bit (11-w)
        #pragma unroll
        for (int w = 8; w < 12; w++) {
            const int bp = 11 - w;
            const ull c2 = sC2[w], s2 = sS2[w], ns2 = sNS2[w];
            #pragma unroll
            for (int k0 = 0; k0 < 16; k0++) {
                if (k0 & (1 << bp)) continue;
                const int k1 = k0 | (1 << bp);
                bflyr(A[k0], A[k1], c2, s2, ns2);
            }
        }

        // transpose A -> B (128-bit write on A side, 64-bit read on B side)
        __syncthreads();
        #pragma unroll
        for (int p = 0; p < 8; p++)
            st2[(tid << 3) | (p ^ t3)] = make_ulonglong2(A[2*p], A[2*p+1]);
        __syncthreads();
        #pragma unroll
        for (int k = 0; k < 16; k++)
            A[k] = stu[(k << 8) | tB];

        // B-phase reg: wires 0..3 on k bit (3-w)
        #pragma unroll
        for (int w = 0; w < 4; w++) {
            const int bp = 3 - w;
            const ull c2 = sC2[w], s2 = sS2[w], ns2 = sNS2[w];
            #pragma unroll
            for (int k0 = 0; k0 < 16; k0++) {
                if (k0 & (1 << bp)) continue;
                const int k1 = k0 | (1 << bp);
                bflyr(A[k0], A[k1], c2, s2, ns2);
            }
        }

        if (layer == 1) {
            // fused CNOT-ring perm back to mapping A (64-bit write, 128-bit read)
            __syncthreads();
            #pragma unroll
            for (int k = 0; k < 16; k++)
                stu[PLtid ^ PK.v[k]] = A[k];
            __syncthreads();
            #pragma unroll
            for (int p = 0; p < 8; p++) {
                ulonglong2 v = st2[(tid << 3) | (p ^ t3)];
                A[2*p]   = v.x;
                A[2*p+1] = v.y;
            }
            // apply diagonal G per amp
            #pragma unroll
            for (int k = 0; k < 16; k++) {
                float2 g = cmul(T01g[k & 3],
                                ((k >> 1) & 1) ? T23v1[k >> 2] : T23v0[k >> 2]);
                ull gx2  = pk2(g.x, g.x);
                ull gyn2 = pk2(-g.y, g.y);
                A[k] = fma2p(gx2, A[k], mul2p(gyn2, swp(A[k])));
            }
        }
    }

    // ===== Z expectations in mapping B, final perm folded into signs =====
    float SA = 0.f, SB = 0.f, SC = 0.f, SD = 0.f;
    #pragma unroll
    for (int k = 0; k < 16; k++) {
        float2 v = unpk(A[k]);
        float pr = v.x * v.x + v.y * v.y;
        const int k0 = k & 1, k1 = (k >> 1) & 1, k2 = (k >> 2) & 1, k3 = k >> 3;
        SA += (k0 ^ k1 ^ k2)      ? -pr : pr;
        SB += (k2 ^ k3)           ? -pr : pr;
        SC += (k1 ^ k2 ^ k3)      ? -pr : pr;
        SD += (k0 ^ k1 ^ k2 ^ k3) ? -pr : pr;
    }
    float zl[NQ];
    {
        const int ptid = __popc(tid) & 1;
        zl[0] = ptid ? -SA : SA;
        zl[1] = SB;
        zl[2] = SC;
        zl[3] = SD;
        #pragma unroll
        for (int w = 4; w < 12; w++) {
            const int j = 11 - w;
            zl[w] = (__popc(tid >> j) & 1) ? -SD : SD;
        }
    }

    // packed warp reduction: 6 ull lanes carry 12 wires
    {
        ull zp[6];
        #pragma unroll
        for (int i = 0; i < 6; i++) zp[i] = pk2(zl[i], zl[i + 6]);
        #pragma unroll
        for (int off = 16; off > 0; off >>= 1) {
            #pragma unroll
            for (int i = 0; i < 6; i++)
                zp[i] = add2p(zp[i], __shfl_xor_sync(0xFFFFFFFFu, zp[i], off));
        }
        if (lane == 0) {
            #pragma unroll
            for (int i = 0; i < 6; i++) {
                float2 v = unpk(zp[i]);
                zred[i][warp]     = v.x;
                zred[i + 6][warp] = v.y;
            }
        }
    }
    __syncthreads();
    if (tid < NQ) {
        float z = 0.f;
        #pragma unroll
        for (int j = 0; j < BLK / 32; j++) z += zred[tid][j];
        zfin[tid] = z;
    }
    __syncthreads();

    // ---- MLP layer 1: h = relu(z @ w1^T + b1) ----
    if (tid < HID) {
        float h = b1[tid];
        #pragma unroll
        for (int i = 0; i < NQ; i++) h += zfin[i] * w1[tid * NQ + i];
        hbuf[tid] = fmaxf(h, 0.f);
    }
    __syncthreads();

    // ---- MLP layer 2, warp-cooperative coalesced GEMV ----
    {
        float* ob = (float*)st;
        const int half = lane >> 4;
        const int l16  = lane & 15;
        const float4 hv = ((const float4*)hbuf)[l16];
        #pragma unroll
        for (int r = 0; r < 16; r++) {
            const int row = warp * 32 + r * 2 + half;
            float4 wv = *(const float4*)(w2 + row * HID + l16 * 4);
            float s = wv.x * hv.x + wv.y * hv.y + wv.z * hv.z + wv.w * hv.w;
            s += __shfl_xor_sync(0xFFFFFFFFu, s, 1);
            s += __shfl_xor_sync(0xFFFFFFFFu, s, 2);
            s += __shfl_xor_sync(0xFFFFFFFFu, s, 4);
            s += __shfl_xor_sync(0xFFFFFFFFu, s, 8);
            if (l16 == 0) ob[row] = s;
        }
        __syncthreads();
        out[b * OUTDIM + tid] = ob[tid] + b2[tid];
    }
}

extern "C" void kernel_launch(void* const* d_in, const int* in_sizes, int n_in,
                              void* d_out, int out_size) {
    const float* x  = (const float*)d_in[0];
    const float* rw = (const float*)d_in[1];
    const float* rb = (const float*)d_in[2];
    const float* w1 = (const float*)d_in[3];
    const float* b1 = (const float*)d_in[4];
    const float* w2 = (const float*)d_in[5];
    const float* b2 = (const float*)d_in[6];
    float* out = (float*)d_out;
    int batch = in_sizes[0] / 48;
    quantum_reupload_kernel<<<batch, BLK>>>(x, rw, rb, w1, b1, w2, b2, out);
}

// round 13
// speedup vs baseline: 5.1203x; 1.0580x over previous
#include <cuda_runtime.h>
#include <cuda_bf16.h>

#define NQ        12
#define BLK       256
#define OUTDIM    256
#define HID       64

typedef unsigned long long ull;

__device__ __forceinline__ float2 cmul(float2 a, float2 b) {
    return make_float2(a.x * b.x - a.y * b.y, a.x * b.y + a.y * b.x);
}
__device__ __forceinline__ float2 cjf(float2 e, int c) {
    return c ? make_float2(e.x, -e.y) : e;
}

// ---- packed f32x2 helpers ----
__device__ __forceinline__ ull pk2(float lo, float hi) {
    ull r; asm("mov.b64 %0, {%1, %2};" : "=l"(r) : "f"(lo), "f"(hi)); return r;
}
__device__ __forceinline__ float2 unpk(ull v) {
    float lo, hi; asm("mov.b64 {%0, %1}, %2;" : "=f"(lo), "=f"(hi) : "l"(v));
    return make_float2(lo, hi);
}
__device__ __forceinline__ ull swp(ull v) {
    ull r;
    asm("{\n\t.reg .b32 lo, hi;\n\tmov.b64 {lo, hi}, %1;\n\tmov.b64 %0, {hi, lo};\n\t}"
        : "=l"(r) : "l"(v));
    return r;
}
__device__ __forceinline__ ull fma2p(ull a, ull b, ull c) {
    ull r; asm("fma.rn.f32x2 %0, %1, %2, %3;" : "=l"(r) : "l"(a), "l"(b), "l"(c));
    return r;
}
__device__ __forceinline__ ull mul2p(ull a, ull b) {
    ull r; asm("mul.rn.f32x2 %0, %1, %2;" : "=l"(r) : "l"(a), "l"(b)); return r;
}
__device__ __forceinline__ ull add2p(ull a, ull b) {
    ull r; asm("add.rn.f32x2 %0, %1, %2;" : "=l"(r) : "l"(a), "l"(b)); return r;
}

// real-rotation butterfly: a0' = c a0 - s a1 ; a1' = s a0 + c a1  (packed complex amps)
__device__ __forceinline__ void bflyr(ull& a0, ull& a1, ull c2, ull s2, ull ns2) {
    ull n0 = fma2p(ns2, a1, mul2p(c2, a0));
    ull n1 = fma2p(c2,  a1, mul2p(s2, a0));
    a0 = n0; a1 = n1;
}

// CNOT-ring composite: out bit p (p<=10) = XOR of in bits p..11; bit 11 = XOR of bits 0..10.
__host__ __device__ constexpr int Lmap(int b) {
    int r = 0;
    for (int p = 0; p <= 10; p++) {
        int par = 0;
        for (int q = p; q <= 11; q++) par ^= (b >> q) & 1;
        r |= par << p;
    }
    int par = 0;
    for (int q = 0; q <= 10; q++) par ^= (b >> q) & 1;
    return r | (par << 11);
}
__host__ __device__ constexpr int swzB(int x) { return x ^ (((x >> 4) & 7) << 1); }
struct PKt { int v[16]; };
__host__ __device__ constexpr PKt mkPK() {
    PKt t{};
    for (int k = 0; k < 16; k++) t.v[k] = swzB(Lmap(k << 8));
    return t;
}

__global__ __launch_bounds__(BLK, 4) void quantum_reupload_kernel(
    const float* __restrict__ x,    // [B, 48]
    const float* __restrict__ rw,   // [12, 3, 4]
    const float* __restrict__ rb,   // [12, 3]
    const float* __restrict__ w1,   // [64, 12]
    const float* __restrict__ b1,   // [64]
    const float* __restrict__ w2,   // [256, 64]
    const float* __restrict__ b2,   // [256]
    float* __restrict__ out)        // [B, 256]
{
    __shared__ __align__(16) float2 st[4096];   // 32 KB exchange buffer
    __shared__ float2 sU10[NQ];                 // e^{i phi} sin(th/2)
    __shared__ float  sCh[NQ];                  // cos(th/2)
    __shared__ float2 sEphi[NQ], sElam[NQ];     // e^{i phi}, e^{i lam}
    __shared__ ull    sC2[NQ], sS2[NQ], sNS2[NQ];
    __shared__ float  zred[NQ][BLK/32];
    __shared__ float  zfin[NQ];
    __shared__ __align__(16) float hbuf[HID];

    const int b    = blockIdx.x;
    const int tid  = threadIdx.x;       // 0..255
    const int lane = tid & 31;
    const int warp = tid >> 5;

    constexpr PKt PK = mkPK();          // swzB(L(k<<8)) constants

    // ---- per-batch U3 angles (layer-invariant) ----
    if (tid < NQ) {
        const float* xb  = x  + b * 48 + tid * 4;
        const float* rwi = rw + tid * 12;
        const float* rbi = rb + tid * 3;
        float x0 = xb[0], x1 = xb[1], x2 = xb[2], x3 = xb[3];
        float th = rbi[0] + rwi[0]*x0 + rwi[1]*x1 + rwi[2] *x2 + rwi[3] *x3;
        float ph = rbi[1] + rwi[4]*x0 + rwi[5]*x1 + rwi[6] *x2 + rwi[7] *x3;
        float lm = rbi[2] + rwi[8]*x0 + rwi[9]*x1 + rwi[10]*x2 + rwi[11]*x3;
        float sh, ch, sp, cp, sl, cl;
        sincosf(th * 0.5f, &sh, &ch);
        sincosf(ph,        &sp, &cp);
        sincosf(lm,        &sl, &cl);
        sCh[tid]   = ch;
        sU10[tid]  = make_float2(cp * sh, sp * sh);
        sEphi[tid] = make_float2(cp, sp);
        sElam[tid] = make_float2(cl, sl);
        sC2[tid]   = pk2(ch, ch);
        sS2[tid]   = pk2(sh, sh);
        sNS2[tid]  = pk2(-sh, -sh);
    }
    __syncthreads();

    // L(tid part) via suffix parity over 8 bits + bit 11 = parity(tid)
    int y = tid; y ^= y >> 1; y ^= y >> 2; y ^= y >> 4;
    const int Ltid  = (y & 0xFF) | ((y & 1) << 11);
    const int PLtid = swzB(Ltid);
    const int t3    = tid & 7;                          // A-side f4 slot xor key
    const int tB    = tid ^ (((tid >> 4) & 7) << 1);    // B-read addr part
    const int cb    = ((tid >> 4) << 8) | (tid & 15);   // C-mapping base

    const int t0 = tid & 1, t1 = (tid >> 1) & 1, t2 = (tid >> 2) & 1,
              t3b = (tid >> 3) & 1, t4 = (tid >> 4) & 1, t5 = (tid >> 5) & 1,
              t6 = (tid >> 6) & 1, t7 = (tid >> 7) & 1;

    ull A[16];
    ull*        stu = (ull*)st;
    ulonglong2* st2 = (ulonglong2*)st;

    auto col0 = [&](int w, int bit) -> float2 {
        return bit ? sU10[w] : make_float2(sCh[w], 0.f);
    };

    // ===== build of (Lam1 ∘ perm ∘ layer-0-U3) state in mapping A =====
    {
        float2 base = col0(2, t5 ^ t6);
        base = cmul(base, col0(3, t4 ^ t5));
        base = cmul(base, col0(4, t3b ^ t4));
        base = cmul(base, col0(5, t2 ^ t3b));
        base = cmul(base, col0(6, t1 ^ t2));
        base = cmul(base, col0(7, t0 ^ t1));
        if (t7)  base = cmul(base, sElam[0]);
        if (t6)  base = cmul(base, sElam[1]);
        if (t5)  base = cmul(base, sElam[2]);
        if (t4)  base = cmul(base, sElam[3]);
        if (t3b) base = cmul(base, sElam[4]);
        if (t2)  base = cmul(base, sElam[5]);
        if (t1)  base = cmul(base, sElam[6]);
        if (t0)  base = cmul(base, sElam[7]);

        float2 baseG[2];
        #pragma unroll
        for (int k0 = 0; k0 < 2; k0++) {
            float2 g = cmul(col0(0, k0 ^ t7), col0(1, k0 ^ t6 ^ t7));
            baseG[k0] = cmul(base, g);
        }
        float2 bG4[4];
        bG4[0] = baseG[0];
        bG4[1] = cmul(baseG[1], sElam[11]);
        bG4[2] = cmul(baseG[0], sElam[10]);
        bG4[3] = cmul(bG4[1],   sElam[10]);

        float2 Qhi[4], Qlo[4];
        #pragma unroll
        for (int i = 0; i < 4; i++) {
            int m3 = i >> 1, m2 = i & 1;
            Qhi[i] = cmul(col0(8, m3 ^ t0), col0(9, m2));
            int m1 = i >> 1, m0 = i & 1;
            Qlo[i] = cmul(col0(10, m1), col0(11, m0));
        }
        Qhi[1] = cmul(Qhi[1], sElam[9]);
        Qhi[2] = cmul(Qhi[2], cmul(sElam[8], sElam[9]));
        Qhi[3] = cmul(Qhi[3], sElam[8]);

        #pragma unroll
        for (int k = 0; k < 16; k++) {
            const int k0 = k & 1, k1 = (k >> 1) & 1, k2 = (k >> 2) & 1, k3 = k >> 3;
            const int m3 = k3, m2 = k2 ^ k3, m1 = k1 ^ k2, m0 = k0 ^ k1;
            float2 v = cmul(bG4[k & 3], cmul(Qhi[(m3 << 1) | m2], Qlo[(m1 << 1) | m0]));
            A[k] = pk2(v.x, v.y);
        }
    }

    // ===== layers 1,2 — all gates register-local via A/C/B mappings =====
    #pragma unroll
    for (int layer = 1; layer < 3; layer++) {
        // A-phase reg: wires 8..11 on k bit (11-w)
        #pragma unroll
        for (int w = 8; w < 12; w++) {
            const int bp = 11 - w;
            const ull c2 = sC2[w], s2 = sS2[w], ns2 = sNS2[w];
            #pragma unroll
            for (int k0 = 0; k0 < 16; k0++) {
                if (k0 & (1 << bp)) continue;
                const int k1 = k0 | (1 << bp);
                bflyr(A[k0], A[k1], c2, s2, ns2);
            }
        }

        // RT A -> C (128-bit write, 64-bit read; uniform swzB phys space)
        __syncthreads();
        #pragma unroll
        for (int p = 0; p < 8; p++)
            st2[(tid << 3) | (p ^ t3)] = make_ulonglong2(A[2*p], A[2*p+1]);
        __syncthreads();
        #pragma unroll
        for (int k = 0; k < 16; k++)
            A[k] = stu[cb ^ ((k << 4) | ((k & 7) << 1))];

        // C-phase reg: wires 4..7 on k bit (7-w)
        #pragma unroll
        for (int w = 4; w < 8; w++) {
            const int bp = 7 - w;
            const ull c2 = sC2[w], s2 = sS2[w], ns2 = sNS2[w];
            #pragma unroll
            for (int k0 = 0; k0 < 16; k0++) {
                if (k0 & (1 << bp)) continue;
                const int k1 = k0 | (1 << bp);
                bflyr(A[k0], A[k1], c2, s2, ns2);
            }
        }

        // RT C -> B (64-bit both sides)
        __syncthreads();
        #pragma unroll
        for (int k = 0; k < 16; k++)
            stu[cb ^ ((k << 4) | ((k & 7) << 1))] = A[k];
        __syncthreads();
        #pragma unroll
        for (int k = 0; k < 16; k++)
            A[k] = stu[(k << 8) | tB];

        // B-phase reg: wires 0..3 on k bit (3-w)
        #pragma unroll
        for (int w = 0; w < 4; w++) {
            const int bp = 3 - w;
            const ull c2 = sC2[w], s2 = sS2[w], ns2 = sNS2[w];
            #pragma unroll
            for (int k0 = 0; k0 < 16; k0++) {
                if (k0 & (1 << bp)) continue;
                const int k1 = k0 | (1 << bp);
                bflyr(A[k0], A[k1], c2, s2, ns2);
            }
        }

        if (layer == 1) {
            // fused CNOT-ring perm back to mapping A (64-bit write, 128-bit read)
            __syncthreads();
            #pragma unroll
            for (int k = 0; k < 16; k++)
                stu[PLtid ^ PK.v[k]] = A[k];
            __syncthreads();
            #pragma unroll
            for (int p = 0; p < 8; p++) {
                ulonglong2 v = st2[(tid << 3) | (p ^ t3)];
                A[2*p]   = v.x;
                A[2*p+1] = v.y;
            }

            // G = (Phi1 relabeled by L^{-1}) * Lam2 — built at point of use
            float2 T01g[4], T23v0[4], T23v1[4];
            {
                float2 gt = make_float2(1.f, 0.f);
                if (t5 ^ t6)  gt = cmul(gt, sEphi[2]);
                if (t4 ^ t5)  gt = cmul(gt, sEphi[3]);
                if (t3b ^ t4) gt = cmul(gt, sEphi[4]);
                if (t2 ^ t3b) gt = cmul(gt, sEphi[5]);
                if (t1 ^ t2)  gt = cmul(gt, sEphi[6]);
                if (t0 ^ t1)  gt = cmul(gt, sEphi[7]);
                if (t7)  gt = cmul(gt, sElam[0]);
                if (t6)  gt = cmul(gt, sElam[1]);
                if (t5)  gt = cmul(gt, sElam[2]);
                if (t4)  gt = cmul(gt, sElam[3]);
                if (t3b) gt = cmul(gt, sElam[4]);
                if (t2)  gt = cmul(gt, sElam[5]);
                if (t1)  gt = cmul(gt, sElam[6]);
                if (t0)  gt = cmul(gt, sElam[7]);
                if (t7)       gt = cmul(gt, sEphi[0]);
                if (t6 ^ t7)  gt = cmul(gt, sEphi[1]);
                if (t0)       gt = cmul(gt, sEphi[8]);

                float2 E0 = cmul(sElam[11], cmul(cjf(sEphi[0], t7), cjf(sEphi[1], t6 ^ t7)));
                float2 E1 = sElam[10];
                float2 E2 = sElam[9];
                float2 E3 = cmul(sElam[8], cjf(sEphi[8], t0));
                float2 X01 = sEphi[11], X12 = sEphi[10], X23 = sEphi[9];

                T01g[0] = gt;
                T01g[1] = cmul(gt, cmul(E0, X01));
                T01g[2] = cmul(gt, cmul(E1, X01));
                T01g[3] = cmul(gt, cmul(E0, E1));

                float2 e2x = cmul(E2, X23);
                float2 e3x = cmul(E3, X23);
                float2 e23 = cmul(E2, E3);
                T23v0[0] = make_float2(1.f, 0.f);
                T23v0[1] = cmul(e2x, X12);
                T23v0[2] = e3x;
                T23v0[3] = cmul(e23, X12);
                T23v1[0] = X12;
                T23v1[1] = e2x;
                T23v1[2] = cmul(e3x, X12);
                T23v1[3] = e23;
            }
            #pragma unroll
            for (int k = 0; k < 16; k++) {
                float2 g = cmul(T01g[k & 3],
                                ((k >> 1) & 1) ? T23v1[k >> 2] : T23v0[k >> 2]);
                ull gx2  = pk2(g.x, g.x);
                ull gyn2 = pk2(-g.y, g.y);
                A[k] = fma2p(gx2, A[k], mul2p(gyn2, swp(A[k])));
            }
        }
    }

    // ===== Z expectations in mapping B, final perm folded into signs =====
    float SA = 0.f, SB = 0.f, SC = 0.f, SD = 0.f;
    #pragma unroll
    for (int k = 0; k < 16; k++) {
        float2 v = unpk(A[k]);
        float pr = v.x * v.x + v.y * v.y;
        const int k0 = k & 1, k1 = (k >> 1) & 1, k2 = (k >> 2) & 1, k3 = k >> 3;
        SA += (k0 ^ k1 ^ k2)      ? -pr : pr;
        SB += (k2 ^ k3)           ? -pr : pr;
        SC += (k1 ^ k2 ^ k3)      ? -pr : pr;
        SD += (k0 ^ k1 ^ k2 ^ k3) ? -pr : pr;
    }
    float zl[NQ];
    {
        const int ptid = __popc(tid) & 1;
        zl[0] = ptid ? -SA : SA;
        zl[1] = SB;
        zl[2] = SC;
        zl[3] = SD;
        #pragma unroll
        for (int w = 4; w < 12; w++) {
            const int j = 11 - w;
            zl[w] = (__popc(tid >> j) & 1) ? -SD : SD;
        }
    }

    // packed warp reduction: 6 ull lanes carry 12 wires
    {
        ull zp[6];
        #pragma unroll
        for (int i = 0; i < 6; i++) zp[i] = pk2(zl[i], zl[i + 6]);
        #pragma unroll
        for (int off = 16; off > 0; off >>= 1) {
            #pragma unroll
            for (int i = 0; i < 6; i++)
                zp[i] = add2p(zp[i], __shfl_xor_sync(0xFFFFFFFFu, zp[i], off));
        }
        if (lane == 0) {
            #pragma unroll
            for (int i = 0; i < 6; i++) {
                float2 v = unpk(zp[i]);
                zred[i][warp]     = v.x;
                zred[i + 6][warp] = v.y;
            }
        }
    }
    __syncthreads();
    if (tid < NQ) {
        float z = 0.f;
        #pragma unroll
        for (int j = 0; j < BLK / 32; j++) z += zred[tid][j];
        zfin[tid] = z;
    }
    __syncthreads();

    // ---- MLP layer 1: h = relu(z @ w1^T + b1) ----
    if (tid < HID) {
        float h = b1[tid];
        #pragma unroll
        for (int i = 0; i < NQ; i++) h += zfin[i] * w1[tid * NQ + i];
        hbuf[tid] = fmaxf(h, 0.f);
    }
    __syncthreads();

    // ---- MLP layer 2, warp-cooperative coalesced GEMV ----
    {
        float* ob = (float*)st;
        const int half = lane >> 4;
        const int l16  = lane & 15;
        const float4 hv = ((const float4*)hbuf)[l16];
        #pragma unroll
        for (int r = 0; r < 16; r++) {
            const int row = warp * 32 + r * 2 + half;
            float4 wv = *(const float4*)(w2 + row * HID + l16 * 4);
            float s = wv.x * hv.x + wv.y * hv.y + wv.z * hv.z + wv.w * hv.w;
            s += __shfl_xor_sync(0xFFFFFFFFu, s, 1);
            s += __shfl_xor_sync(0xFFFFFFFFu, s, 2);
            s += __shfl_xor_sync(0xFFFFFFFFu, s, 4);
            s += __shfl_xor_sync(0xFFFFFFFFu, s, 8);
            if (l16 == 0) ob[row] = s;
        }
        __syncthreads();
        out[b * OUTDIM + tid] = ob[tid] + b2[tid];
    }
}

extern "C" void kernel_launch(void* const* d_in, const int* in_sizes, int n_in,
                              void* d_out, int out_size) {
    const float* x  = (const float*)d_in[0];
    const float* rw = (const float*)d_in[1];
    const float* rb = (const float*)d_in[2];
    const float* w1 = (const float*)d_in[3];
    const float* b1 = (const float*)d_in[4];
    const float* w2 = (const float*)d_in[5];
    const float* b2 = (const float*)d_in[6];
    float* out = (float*)d_out;
    int batch = in_sizes[0] / 48;
    quantum_reupload_kernel<<<batch, BLK>>>(x, rw, rb, w1, b1, w2, b2, out);
}